// round 12
// baseline (speedup 1.0000x reference)
#include <cuda_runtime.h>
#include <cuda_fp16.h>
#include <cstdint>
#include <cstddef>

#define HIDDEN 1024
#define INTER  4096
#define MTOT_MAX 16384

// ---------------- scratch (device globals; no allocation allowed) ----------------
__device__ __align__(256) __half g_acth[(size_t)MTOT_MAX * INTER];   // 128 MB
__device__ __align__(256) __half g_xh [(size_t)MTOT_MAX * HIDDEN];   // 32 MB
__device__ __align__(256) __half g_w1h[(size_t)INTER * HIDDEN];      // 8 MB
__device__ __align__(256) __half g_w2h[(size_t)HIDDEN * INTER];      // 8 MB

// ---------------- tile config (R10 shape: 256 thr, 8 warps 2Mx4N of 64x32) -------
static constexpr int TILE_M = 128;
static constexpr int TILE_N = 128;
static constexpr int TILE_K = 64;                       // 64 fp16 = 128 B rows
static constexpr int NSTAGE = 3;
static constexpr int STAGE_A_BYTES = TILE_M * TILE_K * 2;   // 16 KB
static constexpr int STAGE_B_BYTES = TILE_N * TILE_K * 2;   // 16 KB
static constexpr int STAGE_BYTES   = STAGE_A_BYTES + STAGE_B_BYTES; // 32 KB
static constexpr int SMEM_TOTAL    = NSTAGE * STAGE_BYTES;  // 96 KB -> 2 CTAs/SM
static constexpr int NTHREADS = 256;

// ---------------- helpers ----------------
__device__ __forceinline__ uint32_t smem_u32(const void* p) {
    uint32_t a;
    asm("{ .reg .u64 t; cvta.to.shared.u64 t, %1; cvt.u32.u64 %0, t; }" : "=r"(a) : "l"(p));
    return a;
}
__device__ __forceinline__ void cp16(uint32_t s, const void* g) {
    asm volatile("cp.async.cg.shared.global [%0], [%1], 16;" :: "r"(s), "l"(g) : "memory");
}
__device__ __forceinline__ void cp_commit() { asm volatile("cp.async.commit_group;" ::: "memory"); }
template<int N_> __device__ __forceinline__ void cp_wait() {
    asm volatile("cp.async.wait_group %0;" :: "n"(N_) : "memory");
}

// ---------------- mma.sync m16n8k16 fp16 -> fp32 acc ----------------
__device__ __forceinline__ void mma_f16(float* c, const uint32_t* a, const uint32_t* b) {
    asm volatile(
        "mma.sync.aligned.m16n8k16.row.col.f32.f16.f16.f32 "
        "{%0,%1,%2,%3}, {%4,%5,%6,%7}, {%8,%9}, {%0,%1,%2,%3};\n"
        : "+f"(c[0]), "+f"(c[1]), "+f"(c[2]), "+f"(c[3])
        : "r"(a[0]), "r"(a[1]), "r"(a[2]), "r"(a[3]), "r"(b[0]), "r"(b[1]));
}

__device__ __forceinline__ void ldsm4(uint32_t* r, uint32_t addr) {
    asm volatile(
        "ldmatrix.sync.aligned.m8n8.x4.shared.b16 {%0,%1,%2,%3}, [%4];"
        : "=r"(r[0]), "=r"(r[1]), "=r"(r[2]), "=r"(r[3])
        : "r"(addr));
}

// ---------------- fp32 -> fp16 RN convert (8 elems / thread) ----------------
__global__ void cvt_f16_kernel(const float4* __restrict__ in, uint4* __restrict__ out, int n8) {
    int i = blockIdx.x * blockDim.x + threadIdx.x;
    if (i >= n8) return;
    float4 v0 = in[2 * i];
    float4 v1 = in[2 * i + 1];
    __half2 h0 = __floats2half2_rn(v0.x, v0.y);
    __half2 h1 = __floats2half2_rn(v0.z, v0.w);
    __half2 h2 = __floats2half2_rn(v1.x, v1.y);
    __half2 h3 = __floats2half2_rn(v1.z, v1.w);
    uint4 o;
    o.x = *(uint32_t*)&h0; o.y = *(uint32_t*)&h1;
    o.z = *(uint32_t*)&h2; o.w = *(uint32_t*)&h3;
    out[i] = o;
}

// ---------------- smem addressing ----------------
// Row r holds 64 fp16 = 8 chunks of 16B; chunk ch stored at slot ((ch + r) & 7).
// 8 consecutive rows of a fixed logical chunk hit 8 distinct slots -> LDSM conflict-free.

// tile: 128 rows x 8 chunks = 1024 chunks, 256 thr -> 4 each
__device__ __forceinline__ void load_tile(uint32_t sdst, const __half* __restrict__ G,
                                          int row0, int k0, int ldg, int tid) {
#pragma unroll
    for (int i = 0; i < 4; i++) {
        int ci = tid + i * NTHREADS;
        uint32_t r = (uint32_t)(ci >> 3);
        uint32_t ch = (uint32_t)(ci & 7);
        uint32_t dst = sdst + r * 128u + (((ch + r) & 7u) * 16u);
        cp16(dst, G + (size_t)(row0 + (int)r) * ldg + k0 + (int)ch * 8);
    }
}

// Fragment set for one k16 step: A 4 m-tiles x4 regs, B 4 n-tiles x2 regs.
struct Frags {
    uint32_t a[4][4];
    uint32_t b[4][2];
};

// ---------------- GEMM: C[M,N] = A[M,K] @ B[N,K]^T + bias ----------------
// 256 threads, 8 warps in 2(M) x 4(N); each warp computes 64x32.
// RELU_H: fuse bias+relu, emit fp16 (layer 1). Else bias, emit fp32 (layer 2).
template<bool RELU_H>
__global__ void __launch_bounds__(NTHREADS, 2)
gemm_kernel(const __half* __restrict__ A, const __half* __restrict__ B,
            const float* __restrict__ bias, void* __restrict__ Cv,
            int N, int K)
{
    extern __shared__ char smem[];
    const int tid = threadIdx.x;
    const int wid = tid >> 5;
    const int lid = tid & 31;
    const int wm = wid >> 2;          // 0..1  (64 rows)
    const int wn = wid & 3;           // 0..3  (32 cols)
    const int tr = lid >> 2;          // 0..7
    const int tc = lid & 3;           // 0..3

    const int m0 = blockIdx.y * TILE_M;
    const int n0 = blockIdx.x * TILE_N;
    const int KT = K / TILE_K;

    const uint32_t sbase = smem_u32(smem);

    // LDSM lane bases.
    // A x4 quadrants: [r..r+7, ch][r+8.., ch][r.., ch+1][r+8.., ch+1]
    const uint32_t rowA = (uint32_t)(wm * 64 + (((lid >> 3) & 1) << 3) + (lid & 7));
    const uint32_t chA  = (uint32_t)((lid >> 4) & 1);
    // B x4 quadrants: [n..n+7, ch][n.., ch+1][n+8.., ch][n+8.., ch+1]
    const uint32_t rowB = (uint32_t)(wn * 32 + (((lid >> 4) & 1) << 3) + (lid & 7));
    const uint32_t chB  = (uint32_t)((lid >> 3) & 1);

    float acc[4][4][4];               // [mt][nt][frag] = 64 regs
#pragma unroll
    for (int i = 0; i < 4; i++)
#pragma unroll
        for (int j = 0; j < 4; j++)
#pragma unroll
            for (int f = 0; f < 4; f++) acc[i][j][f] = 0.0f;

    // per-step fragment loader (s = k16 step within the ktile)
    auto ld_frags = [&](Frags& f, uint32_t sA, uint32_t sB, int s) {
        const uint32_t swa = (((uint32_t)(2 * s) + chA + (lid & 7u)) & 7u) * 16u;
        const uint32_t swb = (((uint32_t)(2 * s) + chB + (lid & 7u)) & 7u) * 16u;
#pragma unroll
        for (int mt = 0; mt < 4; mt++)
            ldsm4(f.a[mt], sA + (rowA + (uint32_t)(mt * 16)) * 128u + swa);
#pragma unroll
        for (int p = 0; p < 2; p++) {
            uint32_t t[4];
            ldsm4(t, sB + (rowB + (uint32_t)(p * 16)) * 128u + swb);
            f.b[2 * p][0] = t[0]; f.b[2 * p][1] = t[1];
            f.b[2 * p + 1][0] = t[2]; f.b[2 * p + 1][1] = t[3];
        }
    };
    auto mma_all = [&](const Frags& f) {
#pragma unroll
        for (int mt = 0; mt < 4; mt++)
#pragma unroll
            for (int nt = 0; nt < 4; nt++)
                mma_f16(acc[mt][nt], f.a[mt], f.b[nt]);
    };

    // prologue: stages 0, 1
    load_tile(sbase + 0 * STAGE_BYTES,                 A, m0, 0, K, tid);
    load_tile(sbase + 0 * STAGE_BYTES + STAGE_A_BYTES, B, n0, 0, K, tid);
    cp_commit();
    load_tile(sbase + 1 * STAGE_BYTES,                 A, m0, TILE_K, K, tid);
    load_tile(sbase + 1 * STAGE_BYTES + STAGE_A_BYTES, B, n0, TILE_K, K, tid);
    cp_commit();

    for (int kt = 0; kt < KT; kt++) {
        if (kt + 1 < KT) cp_wait<1>(); else cp_wait<0>();
        __syncthreads();

        const uint32_t sA = sbase + (uint32_t)((kt % NSTAGE) * STAGE_BYTES);
        const uint32_t sB = sA + STAGE_A_BYTES;

        Frags fr0, fr1;
        // issue step-0 LDSMs first; their latency hides behind cp.async issue below
        ld_frags(fr0, sA, sB, 0);

        if (kt + 2 < KT) {
            uint32_t sdst = sbase + ((kt + 2) % NSTAGE) * STAGE_BYTES;
            load_tile(sdst,                 A, m0, (kt + 2) * TILE_K, K, tid);
            load_tile(sdst + STAGE_A_BYTES, B, n0, (kt + 2) * TILE_K, K, tid);
            cp_commit();
        }

        // software-pipelined k16 steps: prefetch s+1 frags before s's MMAs
        ld_frags(fr1, sA, sB, 1);
        mma_all(fr0);
        ld_frags(fr0, sA, sB, 2);
        mma_all(fr1);
        ld_frags(fr1, sA, sB, 3);
        mma_all(fr0);
        mma_all(fr1);
    }

    // epilogue
#pragma unroll
    for (int mt = 0; mt < 4; mt++) {
        int row = m0 + wm * 64 + mt * 16 + tr;
#pragma unroll
        for (int nt = 0; nt < 4; nt++) {
            int col = n0 + wn * 32 + nt * 8 + 2 * tc;
            float b0 = bias[col], b1 = bias[col + 1];
            if (RELU_H) {
                __half* C = (__half*)Cv;
                __half2 h0 = __floats2half2_rn(fmaxf(acc[mt][nt][0] + b0, 0.0f),
                                               fmaxf(acc[mt][nt][1] + b1, 0.0f));
                __half2 h1 = __floats2half2_rn(fmaxf(acc[mt][nt][2] + b0, 0.0f),
                                               fmaxf(acc[mt][nt][3] + b1, 0.0f));
                *(__half2*)(C + (size_t)row * N + col)       = h0;
                *(__half2*)(C + (size_t)(row + 8) * N + col) = h1;
            } else {
                float* C = (float*)Cv;
                float2 v0, v1;
                v0.x = acc[mt][nt][0] + b0;  v0.y = acc[mt][nt][1] + b1;
                v1.x = acc[mt][nt][2] + b0;  v1.y = acc[mt][nt][3] + b1;
                *(float2*)(C + (size_t)row * N + col)       = v0;
                *(float2*)(C + (size_t)(row + 8) * N + col) = v1;
            }
        }
    }
}

// ---------------- launch ----------------
extern "C" void kernel_launch(void* const* d_in, const int* in_sizes, int n_in,
                              void* d_out, int out_size) {
    const float* x  = (const float*)d_in[0];
    const float* W1 = (const float*)d_in[1];
    const float* b1 = (const float*)d_in[2];
    const float* W2 = (const float*)d_in[3];
    const float* b2 = (const float*)d_in[4];
    float* out = (float*)d_out;
    (void)n_in; (void)out_size;

    const int M = in_sizes[0] / HIDDEN;   // 16384

    __half *acth, *xh, *w1h, *w2h;
    cudaGetSymbolAddress((void**)&acth, g_acth);
    cudaGetSymbolAddress((void**)&xh,   g_xh);
    cudaGetSymbolAddress((void**)&w1h,  g_w1h);
    cudaGetSymbolAddress((void**)&w2h,  g_w2h);

    cudaFuncSetAttribute(gemm_kernel<true>,  cudaFuncAttributeMaxDynamicSharedMemorySize, SMEM_TOTAL);
    cudaFuncSetAttribute(gemm_kernel<false>, cudaFuncAttributeMaxDynamicSharedMemorySize, SMEM_TOTAL);

    // fp32 -> fp16 RN operand conversion
    int n8;
    n8 = (M * HIDDEN) / 8;
    cvt_f16_kernel<<<(n8 + 255) / 256, 256>>>((const float4*)x,  (uint4*)xh,  n8);
    n8 = (INTER * HIDDEN) / 8;
    cvt_f16_kernel<<<(n8 + 255) / 256, 256>>>((const float4*)W1, (uint4*)w1h, n8);
    n8 = (HIDDEN * INTER) / 8;
    cvt_f16_kernel<<<(n8 + 255) / 256, 256>>>((const float4*)W2, (uint4*)w2h, n8);

    // GEMM1: act_h = fp16(relu(x @ W1^T + b1))
    gemm_kernel<true><<<dim3(INTER / TILE_N, M / TILE_M), NTHREADS, SMEM_TOTAL>>>(
        xh, w1h, b1, acth, INTER, HIDDEN);

    // GEMM2: out = act_h @ W2^T + b2  (fp32 out)
    gemm_kernel<false><<<dim3(HIDDEN / TILE_N, M / TILE_M), NTHREADS, SMEM_TOTAL>>>(
        acth, w2h, b2, out, HIDDEN, INTER);
}

// round 13
// speedup vs baseline: 1.6650x; 1.6650x over previous
#include <cuda_runtime.h>
#include <cuda_fp16.h>
#include <cstdint>
#include <cstddef>

#define HIDDEN 1024
#define INTER  4096
#define MTOT_MAX 16384

// ---------------- scratch (device globals; no allocation allowed) ----------------
__device__ __align__(256) __half g_acth[(size_t)MTOT_MAX * INTER];   // 128 MB
__device__ __align__(256) __half g_xh [(size_t)MTOT_MAX * HIDDEN];   // 32 MB
__device__ __align__(256) __half g_w1h[(size_t)INTER * HIDDEN];      // 8 MB
__device__ __align__(256) __half g_w2h[(size_t)HIDDEN * INTER];      // 8 MB

// ---------------- tile config (R10 shape: 256 thr, 8 warps 2Mx4N of 64x32) -------
static constexpr int TILE_M = 128;
static constexpr int TILE_N = 128;
static constexpr int TILE_K = 64;                       // 64 fp16 = 128 B rows
static constexpr int NSTAGE = 3;
static constexpr int STAGE_A_BYTES = TILE_M * TILE_K * 2;   // 16 KB
static constexpr int STAGE_B_BYTES = TILE_N * TILE_K * 2;   // 16 KB
static constexpr int STAGE_BYTES   = STAGE_A_BYTES + STAGE_B_BYTES; // 32 KB
static constexpr int SMEM_TOTAL    = NSTAGE * STAGE_BYTES;  // 96 KB -> 2 CTAs/SM
static constexpr int NTHREADS = 256;

// ---------------- helpers ----------------
__device__ __forceinline__ uint32_t smem_u32(const void* p) {
    uint32_t a;
    asm("{ .reg .u64 t; cvta.to.shared.u64 t, %1; cvt.u32.u64 %0, t; }" : "=r"(a) : "l"(p));
    return a;
}
__device__ __forceinline__ void cp16(uint32_t s, const void* g) {
    asm volatile("cp.async.cg.shared.global [%0], [%1], 16;" :: "r"(s), "l"(g) : "memory");
}
__device__ __forceinline__ void cp_commit() { asm volatile("cp.async.commit_group;" ::: "memory"); }
template<int N_> __device__ __forceinline__ void cp_wait() {
    asm volatile("cp.async.wait_group %0;" :: "n"(N_) : "memory");
}

// ---------------- mma.sync m16n8k16 fp16 -> fp32 acc ----------------
__device__ __forceinline__ void mma_f16(float* c, const uint32_t* a, const uint32_t* b) {
    asm volatile(
        "mma.sync.aligned.m16n8k16.row.col.f32.f16.f16.f32 "
        "{%0,%1,%2,%3}, {%4,%5,%6,%7}, {%8,%9}, {%0,%1,%2,%3};\n"
        : "+f"(c[0]), "+f"(c[1]), "+f"(c[2]), "+f"(c[3])
        : "r"(a[0]), "r"(a[1]), "r"(a[2]), "r"(a[3]), "r"(b[0]), "r"(b[1]));
}

__device__ __forceinline__ void ldsm4(uint32_t* r, uint32_t addr) {
    asm volatile(
        "ldmatrix.sync.aligned.m8n8.x4.shared.b16 {%0,%1,%2,%3}, [%4];"
        : "=r"(r[0]), "=r"(r[1]), "=r"(r[2]), "=r"(r[3])
        : "r"(addr));
}

// ---------------- fp32 -> fp16 RN convert (8 elems / thread) ----------------
__global__ void cvt_f16_kernel(const float4* __restrict__ in, uint4* __restrict__ out, int n8) {
    int i = blockIdx.x * blockDim.x + threadIdx.x;
    if (i >= n8) return;
    float4 v0 = in[2 * i];
    float4 v1 = in[2 * i + 1];
    __half2 h0 = __floats2half2_rn(v0.x, v0.y);
    __half2 h1 = __floats2half2_rn(v0.z, v0.w);
    __half2 h2 = __floats2half2_rn(v1.x, v1.y);
    __half2 h3 = __floats2half2_rn(v1.z, v1.w);
    uint4 o;
    o.x = *(uint32_t*)&h0; o.y = *(uint32_t*)&h1;
    o.z = *(uint32_t*)&h2; o.w = *(uint32_t*)&h3;
    out[i] = o;
}

// ---------------- smem addressing ----------------
// Row r holds 64 fp16 = 8 chunks of 16B; chunk ch stored at slot ((ch + r) & 7).
// 8 consecutive rows of a fixed logical chunk hit 8 distinct slots -> LDSM conflict-free.

// tile: 128 rows x 8 chunks = 1024 chunks, 256 thr -> 4 each
__device__ __forceinline__ void load_tile(uint32_t sdst, const __half* __restrict__ G,
                                          int row0, int k0, int ldg, int tid) {
#pragma unroll
    for (int i = 0; i < 4; i++) {
        int ci = tid + i * NTHREADS;
        uint32_t r = (uint32_t)(ci >> 3);
        uint32_t ch = (uint32_t)(ci & 7);
        uint32_t dst = sdst + r * 128u + (((ch + r) & 7u) * 16u);
        cp16(dst, G + (size_t)(row0 + (int)r) * ldg + k0 + (int)ch * 8);
    }
}

// ---------------- GEMM: C[M,N] = A[M,K] @ B[N,K]^T + bias ----------------
// 256 threads, 8 warps in 2(M) x 4(N); each warp computes 64x32.
// RELU_H: fuse bias+relu, emit fp16 (layer 1). Else bias, emit fp32 (layer 2).
template<bool RELU_H>
__global__ void __launch_bounds__(NTHREADS, 2)
gemm_kernel(const __half* __restrict__ A, const __half* __restrict__ B,
            const float* __restrict__ bias, void* __restrict__ Cv,
            int N, int K)
{
    extern __shared__ char smem[];
    const int tid = threadIdx.x;
    const int wid = tid >> 5;
    const int lid = tid & 31;
    const int wm = wid >> 2;          // 0..1  (64 rows)
    const int wn = wid & 3;           // 0..3  (32 cols)
    const int tr = lid >> 2;          // 0..7
    const int tc = lid & 3;           // 0..3

    const int m0 = blockIdx.y * TILE_M;
    const int n0 = blockIdx.x * TILE_N;
    const int KT = K / TILE_K;

    const uint32_t sbase = smem_u32(smem);

    // LDSM lane bases.
    // A x4 quadrants: [r..r+7, ch][r+8.., ch][r.., ch+1][r+8.., ch+1]
    const uint32_t rowA = (uint32_t)(wm * 64 + (((lid >> 3) & 1) << 3) + (lid & 7));
    const uint32_t chA  = (uint32_t)((lid >> 4) & 1);
    // B x4 quadrants: [n..n+7, ch][n.., ch+1][n+8.., ch][n+8.., ch+1]
    const uint32_t rowB = (uint32_t)(wn * 32 + (((lid >> 4) & 1) << 3) + (lid & 7));
    const uint32_t chB  = (uint32_t)((lid >> 3) & 1);

    float acc[4][4][4];               // 64 regs
#pragma unroll
    for (int i = 0; i < 4; i++)
#pragma unroll
        for (int j = 0; j < 4; j++)
#pragma unroll
            for (int f = 0; f < 4; f++) acc[i][j][f] = 0.0f;

    // rolling fragment buffers: A ping-pong across mt (2x4), B ping-pong across s (2x4x2)
    uint32_t afr[2][4];
    uint32_t bfr[2][4][2];

    // prologue: stages 0, 1
    load_tile(sbase + 0 * STAGE_BYTES,                 A, m0, 0, K, tid);
    load_tile(sbase + 0 * STAGE_BYTES + STAGE_A_BYTES, B, n0, 0, K, tid);
    cp_commit();
    load_tile(sbase + 1 * STAGE_BYTES,                 A, m0, TILE_K, K, tid);
    load_tile(sbase + 1 * STAGE_BYTES + STAGE_A_BYTES, B, n0, TILE_K, K, tid);
    cp_commit();

    for (int kt = 0; kt < KT; kt++) {
        if (kt + 1 < KT) cp_wait<1>(); else cp_wait<0>();
        __syncthreads();

        const uint32_t sA = sbase + (uint32_t)((kt % NSTAGE) * STAGE_BYTES);
        const uint32_t sB = sA + STAGE_A_BYTES;

        // preload step 0: B frags (buffer 0) + A frag mt=0 (buffer 0)
        {
            const uint32_t swb0 = ((chB + (lid & 7u)) & 7u) * 16u;
            const uint32_t swa0 = ((chA + (lid & 7u)) & 7u) * 16u;
            uint32_t t[4];
            ldsm4(t, sB + rowB * 128u + swb0);
            bfr[0][0][0] = t[0]; bfr[0][0][1] = t[1];
            bfr[0][1][0] = t[2]; bfr[0][1][1] = t[3];
            ldsm4(t, sB + (rowB + 16u) * 128u + swb0);
            bfr[0][2][0] = t[0]; bfr[0][2][1] = t[1];
            bfr[0][3][0] = t[2]; bfr[0][3][1] = t[3];
            ldsm4(afr[0], sA + rowA * 128u + swa0);
        }

        // issue next-tile cp.async while the first LDSMs are in flight
        if (kt + 2 < KT) {
            uint32_t sdst = sbase + ((kt + 2) % NSTAGE) * STAGE_BYTES;
            load_tile(sdst,                 A, m0, (kt + 2) * TILE_K, K, tid);
            load_tile(sdst + STAGE_A_BYTES, B, n0, (kt + 2) * TILE_K, K, tid);
            cp_commit();
        }

#pragma unroll
        for (int s = 0; s < 4; s++) {              // 4 x k16 steps
            const int cb = s & 1;                   // current B buffer
            const uint32_t swaS = (((uint32_t)(2 * s)     + chA + (lid & 7u)) & 7u) * 16u;
            const uint32_t swaN = (((uint32_t)(2 * s + 2) + chA + (lid & 7u)) & 7u) * 16u;
            const uint32_t swbN = (((uint32_t)(2 * s + 2) + chB + (lid & 7u)) & 7u) * 16u;

#pragma unroll
            for (int mt = 0; mt < 4; mt++) {
                const int ca = mt & 1;              // current A buffer (4s+mt parity = mt parity)

                // one LDSM volley per MMA group, always >=1 group ahead of use
                if (mt == 0 && s < 3) {             // next step's B frags
                    uint32_t t[4];
                    ldsm4(t, sB + rowB * 128u + swbN);
                    bfr[cb ^ 1][0][0] = t[0]; bfr[cb ^ 1][0][1] = t[1];
                    bfr[cb ^ 1][1][0] = t[2]; bfr[cb ^ 1][1][1] = t[3];
                    ldsm4(t, sB + (rowB + 16u) * 128u + swbN);
                    bfr[cb ^ 1][2][0] = t[0]; bfr[cb ^ 1][2][1] = t[1];
                    bfr[cb ^ 1][3][0] = t[2]; bfr[cb ^ 1][3][1] = t[3];
                }
                if (mt < 3) {                        // next mt's A frag, same step
                    ldsm4(afr[ca ^ 1], sA + (rowA + (uint32_t)((mt + 1) * 16)) * 128u + swaS);
                } else if (s < 3) {                  // first A frag of next step
                    ldsm4(afr[ca ^ 1], sA + rowA * 128u + swaN);
                }

#pragma unroll
                for (int nt = 0; nt < 4; nt++)
                    mma_f16(acc[mt][nt], afr[ca], bfr[cb][nt]);
            }
        }
    }

    // epilogue
#pragma unroll
    for (int mt = 0; mt < 4; mt++) {
        int row = m0 + wm * 64 + mt * 16 + tr;
#pragma unroll
        for (int nt = 0; nt < 4; nt++) {
            int col = n0 + wn * 32 + nt * 8 + 2 * tc;
            float b0 = bias[col], b1 = bias[col + 1];
            if (RELU_H) {
                __half* C = (__half*)Cv;
                __half2 h0 = __floats2half2_rn(fmaxf(acc[mt][nt][0] + b0, 0.0f),
                                               fmaxf(acc[mt][nt][1] + b1, 0.0f));
                __half2 h1 = __floats2half2_rn(fmaxf(acc[mt][nt][2] + b0, 0.0f),
                                               fmaxf(acc[mt][nt][3] + b1, 0.0f));
                *(__half2*)(C + (size_t)row * N + col)       = h0;
                *(__half2*)(C + (size_t)(row + 8) * N + col) = h1;
            } else {
                float* C = (float*)Cv;
                float2 v0, v1;
                v0.x = acc[mt][nt][0] + b0;  v0.y = acc[mt][nt][1] + b1;
                v1.x = acc[mt][nt][2] + b0;  v1.y = acc[mt][nt][3] + b1;
                *(float2*)(C + (size_t)row * N + col)       = v0;
                *(float2*)(C + (size_t)(row + 8) * N + col) = v1;
            }
        }
    }
}

// ---------------- launch ----------------
extern "C" void kernel_launch(void* const* d_in, const int* in_sizes, int n_in,
                              void* d_out, int out_size) {
    const float* x  = (const float*)d_in[0];
    const float* W1 = (const float*)d_in[1];
    const float* b1 = (const float*)d_in[2];
    const float* W2 = (const float*)d_in[3];
    const float* b2 = (const float*)d_in[4];
    float* out = (float*)d_out;
    (void)n_in; (void)out_size;

    const int M = in_sizes[0] / HIDDEN;   // 16384

    __half *acth, *xh, *w1h, *w2h;
    cudaGetSymbolAddress((void**)&acth, g_acth);
    cudaGetSymbolAddress((void**)&xh,   g_xh);
    cudaGetSymbolAddress((void**)&w1h,  g_w1h);
    cudaGetSymbolAddress((void**)&w2h,  g_w2h);

    cudaFuncSetAttribute(gemm_kernel<true>,  cudaFuncAttributeMaxDynamicSharedMemorySize, SMEM_TOTAL);
    cudaFuncSetAttribute(gemm_kernel<false>, cudaFuncAttributeMaxDynamicSharedMemorySize, SMEM_TOTAL);

    // fp32 -> fp16 RN operand conversion
    int n8;
    n8 = (M * HIDDEN) / 8;
    cvt_f16_kernel<<<(n8 + 255) / 256, 256>>>((const float4*)x,  (uint4*)xh,  n8);
    n8 = (INTER * HIDDEN) / 8;
    cvt_f16_kernel<<<(n8 + 255) / 256, 256>>>((const float4*)W1, (uint4*)w1h, n8);
    n8 = (HIDDEN * INTER) / 8;
    cvt_f16_kernel<<<(n8 + 255) / 256, 256>>>((const float4*)W2, (uint4*)w2h, n8);

    // GEMM1: act_h = fp16(relu(x @ W1^T + b1))
    gemm_kernel<true><<<dim3(INTER / TILE_N, M / TILE_M), NTHREADS, SMEM_TOTAL>>>(
        xh, w1h, b1, acth, INTER, HIDDEN);

    // GEMM2: out = act_h @ W2^T + b2  (fp32 out)
    gemm_kernel<false><<<dim3(HIDDEN / TILE_N, M / TILE_M), NTHREADS, SMEM_TOTAL>>>(
        acth, w2h, b2, out, HIDDEN, INTER);
}